// round 9
// baseline (speedup 1.0000x reference)
#include <cuda_runtime.h>
#include <cuda_bf16.h>
#include <math.h>

// Problem shapes (fixed by the dataset)
#define H    4
#define NN   50000
#define EE   1600000
#define DIN  32
#define DOUT 32
#define NEG_SLOPE 0.2f

// -------- scratch (static device globals; no allocation allowed) --------
__device__ float g_xl[(size_t)H * NN * DOUT];   // 25.6 MB
__device__ float g_xr[(size_t)H * NN * DOUT];   // 25.6 MB
__device__ int   g_cnt[H * NN];
__device__ int   g_offs[H * NN];
__device__ int   g_cursor[H * NN];
__device__ int   g_ssrc[(size_t)H * EE];        // 25.6 MB, CSR-ordered src ids
__device__ int   g_is64;                        // edge_index dtype flag

// ---------------- 0) detect edge_index dtype (int32 vs int64) ----------------
// Genuine int64 node ids are all in [0, NN). int32 data reinterpreted as
// int64 packs two ids per slot -> value >= 2^32 whenever the high half != 0.
__global__ void k_detect(const void* __restrict__ ei) {
    __shared__ int bad;
    if (threadIdx.x == 0) bad = 0;
    __syncthreads();
    const long long* e64 = (const long long*)ei;
    int mybad = 0;
    for (int t = threadIdx.x; t < 1024; t += blockDim.x) {
        long long v = e64[t];                 // first 8KB only — safe either way
        if (v < 0 || v >= NN) mybad = 1;
    }
    if (mybad) atomicOr(&bad, 1);
    __syncthreads();
    if (threadIdx.x == 0) g_is64 = bad ? 0 : 1;
}

__device__ __forceinline__ int load_edge(const void* ei, size_t idx, int is64) {
    if (is64) return (int)((const long long*)ei)[idx];
    return ((const int*)ei)[idx];
}

// ---------------- 1) node transforms: xl = x@Wl, xr = x@Wr ----------------
__global__ void k_transform(const float* __restrict__ x,
                            const float* __restrict__ Wl,
                            const float* __restrict__ Wr) {
    __shared__ float sWl[DIN * DOUT];
    __shared__ float sWr[DIN * DOUT];
    int h = blockIdx.y;
    for (int i = threadIdx.x; i < DIN * DOUT; i += blockDim.x) {
        sWl[i] = Wl[h * DIN * DOUT + i];
        sWr[i] = Wr[h * DIN * DOUT + i];
    }
    __syncthreads();
    int warp = threadIdx.x >> 5, lane = threadIdx.x & 31;
    int n = blockIdx.x * (blockDim.x >> 5) + warp;
    if (n >= NN) return;
    float xv = x[((size_t)h * NN + n) * DIN + lane];
    float al = 0.f, ar = 0.f;
#pragma unroll
    for (int k = 0; k < DIN; k++) {
        float b = __shfl_sync(0xffffffffu, xv, k);
        al = fmaf(b, sWl[k * DOUT + lane], al);
        ar = fmaf(b, sWr[k * DOUT + lane], ar);
    }
    size_t o = ((size_t)h * NN + n) * DOUT + lane;
    g_xl[o] = al;
    g_xr[o] = ar;
}

// ---------------- 2) zero counters ----------------
__global__ void k_zero() {
    int i = blockIdx.x * blockDim.x + threadIdx.x;
    if (i < H * NN) g_cnt[i] = 0;
}

// ---------------- 3) histogram of destinations ----------------
__global__ void k_hist(const void* __restrict__ ei) {
    int t = blockIdx.x * blockDim.x + threadIdx.x;
    if (t >= H * EE) return;
    int is64 = g_is64;
    int h = t / EE;
    int j = t - h * EE;
    int dst = load_edge(ei, (size_t)h * 2 * EE + EE + j, is64);
    if ((unsigned)dst < NN)                   // guard: never crash
        atomicAdd(&g_cnt[h * NN + dst], 1);
}

// ---------------- 4) per-head exclusive scan (one block per head) ----------------
__global__ void k_scan() {
    const int T = 1024;
    int h = blockIdx.x;
    __shared__ int wsum[32];
    __shared__ int s_carry;
    int tid = threadIdx.x, lane = tid & 31, wid = tid >> 5;
    if (tid == 0) s_carry = 0;
    __syncthreads();
    for (int base = 0; base < NN; base += T) {
        int i = base + tid;
        int v = (i < NN) ? g_cnt[h * NN + i] : 0;
        int sv = v;
#pragma unroll
        for (int off = 1; off < 32; off <<= 1) {
            int t2 = __shfl_up_sync(0xffffffffu, sv, off);
            if (lane >= off) sv += t2;
        }
        if (lane == 31) wsum[wid] = sv;
        __syncthreads();
        if (wid == 0) {
            int w = wsum[lane];
#pragma unroll
            for (int off = 1; off < 32; off <<= 1) {
                int t2 = __shfl_up_sync(0xffffffffu, w, off);
                if (lane >= off) w += t2;
            }
            wsum[lane] = w;
        }
        __syncthreads();
        int warp_excl = (wid > 0) ? wsum[wid - 1] : 0;
        int incl = warp_excl + sv;
        int excl = incl - v;
        int carry = s_carry;
        if (i < NN) {
            g_offs[h * NN + i]   = carry + excl;
            g_cursor[h * NN + i] = carry + excl;
        }
        __syncthreads();
        if (tid == T - 1) s_carry = carry + incl;
        __syncthreads();
    }
}

// ---------------- 5) scatter src ids into CSR-by-dst order ----------------
__global__ void k_scatter(const void* __restrict__ ei) {
    int t = blockIdx.x * blockDim.x + threadIdx.x;
    if (t >= H * EE) return;
    int is64 = g_is64;
    int h = t / EE;
    int j = t - h * EE;
    int src = load_edge(ei, (size_t)h * 2 * EE + j, is64);
    int dst = load_edge(ei, (size_t)h * 2 * EE + EE + j, is64);
    if ((unsigned)dst >= NN || (unsigned)src >= NN) return;  // same guard as hist
    int p = atomicAdd(&g_cursor[h * NN + dst], 1);
    g_ssrc[(size_t)h * EE + p] = src;
}

// ---------------- 6) main: warp per (head,node), online softmax ----------------
__global__ void __launch_bounds__(256)
k_main(const float* __restrict__ att, const float* __restrict__ bias,
       float* __restrict__ out) {
    int warp_global = blockIdx.x * (blockDim.x >> 5) + (threadIdx.x >> 5);
    int lane = threadIdx.x & 31;
    if (warp_global >= H * NN) return;
    int h = warp_global / NN;
    int n = warp_global - h * NN;
    int node = h * NN + n;

    float att_d = att[h * DOUT + lane];
    size_t rowo = (size_t)node * DOUT + lane;
    float xr_d = g_xr[rowo];
    float xl_self = g_xl[rowo];

    // self-loop edge (PyG add_self_loops=True)
    float t0 = xl_self + xr_d;
    float c = fmaxf(t0, NEG_SLOPE * t0) * att_d;
#pragma unroll
    for (int off = 16; off; off >>= 1)
        c += __shfl_xor_sync(0xffffffffu, c, off);

    float m = c;          // running max (identical across lanes)
    float s = 1.0f;       // running denom
    float acc = xl_self;  // running weighted sum, lane=dim

    int start = g_offs[node];
    int deg = g_cnt[node];
    const float* __restrict__ xlbase = g_xl + (size_t)h * NN * DOUT;
    const int* __restrict__ ssrc = g_ssrc + (size_t)h * EE;

    for (int b = 0; b < deg; b += 32) {
        int cnt = deg - b; // >=1
        int myidx = b + lane;
        int mysrc = (myidx < deg) ? ssrc[start + myidx] : 0;

        float xlv[32];
        float r[32];
#pragma unroll
        for (int j = 0; j < 32; j++) {
            int sj = __shfl_sync(0xffffffffu, mysrc, j);
            float v = xlbase[(size_t)sj * DOUT + lane]; // coalesced 128B row
            xlv[j] = v;
            float tt = v + xr_d;
            r[j] = fmaxf(tt, NEG_SLOPE * tt) * att_d;
        }
        // batched butterfly all-reduce: 5 shfl rounds reduce all 32 logits
#pragma unroll
        for (int off = 16; off; off >>= 1) {
#pragma unroll
            for (int j = 0; j < 32; j++)
                r[j] += __shfl_xor_sync(0xffffffffu, r[j], off);
        }
        // mask tail edges
#pragma unroll
        for (int j = 0; j < 32; j++)
            if (j >= cnt) r[j] = -INFINITY;
        // batch max + online rescale
        float mb = r[0];
#pragma unroll
        for (int j = 1; j < 32; j++) mb = fmaxf(mb, r[j]);
        float nm = fmaxf(m, mb);
        float scale = __expf(m - nm);
        s *= scale;
        acc *= scale;
        m = nm;
#pragma unroll
        for (int j = 0; j < 32; j++) {
            float w = __expf(r[j] - m); // exp(-inf)=0 masks tail
            s += w;
            acc = fmaf(w, xlv[j], acc);
        }
    }

    // output layout [N, H*DOUT]
    out[(size_t)n * (H * DOUT) + h * DOUT + lane] = acc / s + bias[h * DOUT + lane];
}

// ---------------- launch ----------------
extern "C" void kernel_launch(void* const* d_in, const int* in_sizes, int n_in,
                              void* d_out, int out_size) {
    const float* x        = (const float*)d_in[0];
    const void*  ei       = (const void*)d_in[1];
    const float* Wl       = (const float*)d_in[2];
    const float* Wr       = (const float*)d_in[3];
    const float* att      = (const float*)d_in[4];
    const float* bias     = (const float*)d_in[5];
    float* out            = (float*)d_out;

    k_detect<<<1, 256>>>(ei);
    dim3 gT((NN + 7) / 8, H);
    k_transform<<<gT, 256>>>(x, Wl, Wr);
    k_zero<<<(H * NN + 255) / 256, 256>>>();
    k_hist<<<(H * EE + 255) / 256, 256>>>(ei);
    k_scan<<<H, 1024>>>();
    k_scatter<<<(H * EE + 255) / 256, 256>>>(ei);
    k_main<<<(H * NN + 7) / 8, 256>>>(att, bias, out);
}

// round 10
// speedup vs baseline: 1.3865x; 1.3865x over previous
#include <cuda_runtime.h>
#include <cuda_bf16.h>
#include <math.h>

// Problem shapes (fixed by the dataset)
#define H    4
#define NN   50000
#define EE   1600000
#define DIN  32
#define DOUT 32
#define NEG_SLOPE 0.2f

#define SCAN_B 1024
#define NSC ((H * NN + SCAN_B - 1) / SCAN_B)   // 196 blocks

// -------- scratch (static device globals; no allocation allowed) --------
__device__ float g_xl[(size_t)H * NN * DOUT];   // 25.6 MB
__device__ float g_xr[(size_t)H * NN * DOUT];   // 25.6 MB
__device__ int   g_cnt[H * NN];
__device__ int   g_offs[H * NN];                // GLOBAL offsets into g_ssrc
__device__ int   g_cursor[H * NN];
__device__ int   g_ssrc[(size_t)H * EE];        // CSR-ordered src ids (global)
__device__ int   g_bsum[NSC];
__device__ int   g_bpre[NSC];
__device__ int   g_is64;

// ---------------- 0) detect edge_index dtype (int32 vs int64) ----------------
__global__ void k_detect(const void* __restrict__ ei) {
    __shared__ int bad;
    if (threadIdx.x == 0) bad = 0;
    __syncthreads();
    const long long* e64 = (const long long*)ei;
    int mybad = 0;
    for (int t = threadIdx.x; t < 1024; t += blockDim.x) {
        long long v = e64[t];
        if (v < 0 || v >= NN) mybad = 1;
    }
    if (mybad) atomicOr(&bad, 1);
    __syncthreads();
    if (threadIdx.x == 0) g_is64 = bad ? 0 : 1;
}

__device__ __forceinline__ int load_edge(const void* ei, size_t idx, int is64) {
    if (is64) return (int)((const long long*)ei)[idx];
    return ((const int*)ei)[idx];
}

// ---------------- 1) node transforms: xl = x@Wl, xr = x@Wr ----------------
__global__ void k_transform(const float* __restrict__ x,
                            const float* __restrict__ Wl,
                            const float* __restrict__ Wr) {
    __shared__ float sWl[DIN * DOUT];
    __shared__ float sWr[DIN * DOUT];
    int h = blockIdx.y;
    for (int i = threadIdx.x; i < DIN * DOUT; i += blockDim.x) {
        sWl[i] = Wl[h * DIN * DOUT + i];
        sWr[i] = Wr[h * DIN * DOUT + i];
    }
    __syncthreads();
    int warp = threadIdx.x >> 5, lane = threadIdx.x & 31;
    int n = blockIdx.x * (blockDim.x >> 5) + warp;
    if (n >= NN) return;
    float xv = x[((size_t)h * NN + n) * DIN + lane];
    float al = 0.f, ar = 0.f;
#pragma unroll
    for (int k = 0; k < DIN; k++) {
        float b = __shfl_sync(0xffffffffu, xv, k);
        al = fmaf(b, sWl[k * DOUT + lane], al);
        ar = fmaf(b, sWr[k * DOUT + lane], ar);
    }
    size_t o = ((size_t)h * NN + n) * DOUT + lane;
    g_xl[o] = al;
    g_xr[o] = ar;
}

// ---------------- 2) zero counters ----------------
__global__ void k_zero() {
    int i = blockIdx.x * blockDim.x + threadIdx.x;
    if (i < H * NN) g_cnt[i] = 0;
}

// ---------------- 3) histogram of destinations ----------------
__global__ void k_hist(const void* __restrict__ ei) {
    int t = blockIdx.x * blockDim.x + threadIdx.x;
    if (t >= H * EE) return;
    int is64 = g_is64;
    int h = t / EE;
    int j = t - h * EE;
    int dst = load_edge(ei, (size_t)h * 2 * EE + EE + j, is64);
    if ((unsigned)dst < NN)
        atomicAdd(&g_cnt[h * NN + dst], 1);
}

// ---------------- 4) parallel scan: A) per-block scan ----------------
__global__ void k_scanA() {
    __shared__ int wsum[32];
    int tid = threadIdx.x, lane = tid & 31, wid = tid >> 5;
    int i = blockIdx.x * SCAN_B + tid;
    int v = (i < H * NN) ? g_cnt[i] : 0;
    int sv = v;
#pragma unroll
    for (int off = 1; off < 32; off <<= 1) {
        int t2 = __shfl_up_sync(0xffffffffu, sv, off);
        if (lane >= off) sv += t2;
    }
    if (lane == 31) wsum[wid] = sv;
    __syncthreads();
    if (wid == 0) {
        int w = wsum[lane];
#pragma unroll
        for (int off = 1; off < 32; off <<= 1) {
            int t2 = __shfl_up_sync(0xffffffffu, w, off);
            if (lane >= off) w += t2;
        }
        wsum[lane] = w;
    }
    __syncthreads();
    int excl = sv - v + (wid ? wsum[wid - 1] : 0);
    if (i < H * NN) g_offs[i] = excl;
    if (tid == SCAN_B - 1) g_bsum[blockIdx.x] = excl + v;
}

// ---------------- 4b) scan of block sums (one block) ----------------
__global__ void k_scanB() {
    __shared__ int wsum[32];
    int tid = threadIdx.x, lane = tid & 31, wid = tid >> 5;
    int v = (tid < NSC) ? g_bsum[tid] : 0;
    int sv = v;
#pragma unroll
    for (int off = 1; off < 32; off <<= 1) {
        int t2 = __shfl_up_sync(0xffffffffu, sv, off);
        if (lane >= off) sv += t2;
    }
    if (lane == 31) wsum[wid] = sv;
    __syncthreads();
    if (wid == 0) {
        int w = wsum[lane];
#pragma unroll
        for (int off = 1; off < 32; off <<= 1) {
            int t2 = __shfl_up_sync(0xffffffffu, w, off);
            if (lane >= off) w += t2;
        }
        wsum[lane] = w;
    }
    __syncthreads();
    int excl = sv - v + (wid ? wsum[wid - 1] : 0);
    if (tid < NSC) g_bpre[tid] = excl;
}

// ---------------- 4c) add block prefixes ----------------
__global__ void k_scanC() {
    int i = blockIdx.x * SCAN_B + threadIdx.x;
    if (i >= H * NN) return;
    int off = g_offs[i] + g_bpre[i >> 10];
    g_offs[i]   = off;
    g_cursor[i] = off;
}

// ---------------- 5) scatter src ids into CSR-by-dst order ----------------
__global__ void k_scatter(const void* __restrict__ ei) {
    int t = blockIdx.x * blockDim.x + threadIdx.x;
    if (t >= H * EE) return;
    int is64 = g_is64;
    int h = t / EE;
    int j = t - h * EE;
    int src = load_edge(ei, (size_t)h * 2 * EE + j, is64);
    int dst = load_edge(ei, (size_t)h * 2 * EE + EE + j, is64);
    if ((unsigned)dst >= NN || (unsigned)src >= NN) return;
    int p = atomicAdd(&g_cursor[h * NN + dst], 1);   // p is GLOBAL
    g_ssrc[p] = src;
}

// ---------------- 6) main: warp per (head,node), online softmax ----------------
// Batch of 16 edges. Per-lane logit contributions are reduced with a
// recursive-halving transpose: edge j's full logit lands in lanes j and j+16,
// so exp/masking/rescale run once per batch, not once per edge.
__global__ void __launch_bounds__(256, 2)
k_main(const float* __restrict__ att, const float* __restrict__ bias,
       float* __restrict__ out) {
    int wg = blockIdx.x * (blockDim.x >> 5) + (threadIdx.x >> 5);
    int lane = threadIdx.x & 31;
    if (wg >= H * NN) return;
    int h = wg / NN;
    int n = wg - h * NN;
    int node = wg;

    float p = att[h * DOUT + lane];
    float q = NEG_SLOPE * p;
    bool pos = (p >= 0.f);      // att*lrelu(h) = pos ? max(h*p,h*q) : min(h*p,h*q)
    size_t rowo = (size_t)node * DOUT + lane;
    float xr_d = g_xr[rowo];
    float xl_self = g_xl[rowo];

    // self-loop logit
    float hs = xl_self + xr_d;
    float c = pos ? fmaxf(hs * p, hs * q) : fminf(hs * p, hs * q);
#pragma unroll
    for (int off = 16; off; off >>= 1)
        c += __shfl_xor_sync(0xffffffffu, c, off);

    float m = c;                           // running max (lane-uniform)
    float sdist = (lane == 0) ? 2.0f : 0.f; // distributed denom (x2: halved at end)
    float acc = xl_self;                   // weighted sum, lane=dim

    int start = g_offs[node];
    int deg = g_cnt[node];
    const float* __restrict__ xlb = g_xl + (size_t)h * NN * DOUT;
    const int* __restrict__ ssrcp = g_ssrc;

    for (int b = 0; b < deg; b += 16) {
        int cnt = deg - b;
        int idx = b + (lane & 15);
        int mysrc = (idx < deg) ? ssrcp[start + idx] : 0;

        float r[16], xlv[16];
#pragma unroll
        for (int j = 0; j < 16; j++) {
            int sj = __shfl_sync(0xffffffffu, mysrc, j);
            float v = xlb[(size_t)sj * DOUT + lane];   // coalesced 128B row
            xlv[j] = v;
            float hd = v + xr_d;
            r[j] = pos ? fmaxf(hd * p, hd * q) : fminf(hd * p, hd * q);
        }
        // transpose-reduce: r[j] summed over all 32 lanes -> lane (j), (j+16)
#pragma unroll
        for (int j = 0; j < 16; j++)
            r[j] += __shfl_xor_sync(0xffffffffu, r[j], 16);
#pragma unroll
        for (int j = 0; j < 8; j++) {
            float a = r[j], bb = r[j + 8];
            float send = (lane & 8) ? a : bb;
            float keep = (lane & 8) ? bb : a;
            r[j] = keep + __shfl_xor_sync(0xffffffffu, send, 8);
        }
#pragma unroll
        for (int j = 0; j < 4; j++) {
            float a = r[j], bb = r[j + 4];
            float send = (lane & 4) ? a : bb;
            float keep = (lane & 4) ? bb : a;
            r[j] = keep + __shfl_xor_sync(0xffffffffu, send, 4);
        }
#pragma unroll
        for (int j = 0; j < 2; j++) {
            float a = r[j], bb = r[j + 2];
            float send = (lane & 2) ? a : bb;
            float keep = (lane & 2) ? bb : a;
            r[j] = keep + __shfl_xor_sync(0xffffffffu, send, 2);
        }
        {
            float a = r[0], bb = r[1];
            float send = (lane & 1) ? a : bb;
            float keep = (lane & 1) ? bb : a;
            r[0] = keep + __shfl_xor_sync(0xffffffffu, send, 1);
        }
        float e = r[0];                 // logit of edge (lane & 15)
        if ((lane & 15) >= cnt) e = -INFINITY;   // mask tail

        // batch max (lane-uniform result)
        float mb = e;
#pragma unroll
        for (int off = 16; off; off >>= 1)
            mb = fmaxf(mb, __shfl_xor_sync(0xffffffffu, mb, off));
        float nm = fmaxf(m, mb);
        float scale = __expf(m - nm);
        sdist *= scale;
        acc *= scale;
        m = nm;

        float w = __expf(e - m);        // one MUFU per batch; 0 for masked
        sdist += w;
#pragma unroll
        for (int j = 0; j < 16; j++) {
            float wj = __shfl_sync(0xffffffffu, w, j);
            acc = fmaf(wj, xlv[j], acc);
        }
    }

    // total denom: each edge counted at 2 lanes, self counted 2x at lane 0
    float stot = sdist;
#pragma unroll
    for (int off = 16; off; off >>= 1)
        stot += __shfl_xor_sync(0xffffffffu, stot, off);
    stot *= 0.5f;

    out[(size_t)n * (H * DOUT) + h * DOUT + lane] =
        acc / stot + bias[h * DOUT + lane];
}

// ---------------- launch ----------------
extern "C" void kernel_launch(void* const* d_in, const int* in_sizes, int n_in,
                              void* d_out, int out_size) {
    const float* x        = (const float*)d_in[0];
    const void*  ei       = (const void*)d_in[1];
    const float* Wl       = (const float*)d_in[2];
    const float* Wr       = (const float*)d_in[3];
    const float* att      = (const float*)d_in[4];
    const float* bias     = (const float*)d_in[5];
    float* out            = (float*)d_out;

    k_detect<<<1, 256>>>(ei);
    dim3 gT((NN + 7) / 8, H);
    k_transform<<<gT, 256>>>(x, Wl, Wr);
    k_zero<<<(H * NN + 255) / 256, 256>>>();
    k_hist<<<(H * EE + 255) / 256, 256>>>(ei);
    k_scanA<<<NSC, SCAN_B>>>();
    k_scanB<<<1, SCAN_B>>>();
    k_scanC<<<NSC, SCAN_B>>>();
    k_scatter<<<(H * EE + 255) / 256, 256>>>(ei);
    k_main<<<(H * NN + 7) / 8, 256>>>(att, bias, out);
}